// round 16
// baseline (speedup 1.0000x reference)
#include <cuda_runtime.h>
#include <cuda_fp16.h>
#include <cstdint>

#define BATCH 8
#define NT 1024
#define DIM 768
#define NH 12
#define HD 64
#define SCALE 0.125f
#define NBH (BATCH * NH)

// scratch (allocation-free rule: __device__ globals)
__device__ __half g_qh[NBH * NT * HD];                // Q fp16 [bh][t][d]
__device__ __half g_kh[NBH * NT * HD];                // K fp16 [bh][t][d]
__device__ __half g_vt[NBH * HD * NT];                // V fp16 transposed [bh][d][t]
__device__ __half g_xh[BATCH * NT * DIM];             // attention output, fp16
__device__ __half g_tfh[BATCH * NT * DIM];            // fp16 tfeat
__device__ __half g_wh[4 * DIM * DIM];                // fp16 wq,wk,wv,wp
__device__ __half g_p[(size_t)NBH * NT * NT];         // unnormalized exp scores, fp16

// ---------------------------------------------------------------------------
// helpers
// ---------------------------------------------------------------------------
__device__ __forceinline__ uint32_t h2_as_u32(__half2 h) {
    union { __half2 h2; uint32_t u; } cvt;
    cvt.h2 = h;
    return cvt.u;
}

__device__ __forceinline__ void cp16(uint32_t s, const void* g) {
    asm volatile("cp.async.cg.shared.global [%0], [%1], 16;" :: "r"(s), "l"(g));
}
__device__ __forceinline__ void cp_commit() { asm volatile("cp.async.commit_group;"); }
template <int N> __device__ __forceinline__ void cp_wait() {
    asm volatile("cp.async.wait_group %0;" :: "n"(N));
}

__device__ __forceinline__ void mma16(float* c,
                                      uint32_t a0, uint32_t a1, uint32_t a2, uint32_t a3,
                                      uint32_t b0, uint32_t b1) {
    asm volatile(
        "mma.sync.aligned.m16n8k16.row.col.f32.f16.f16.f32 "
        "{%0,%1,%2,%3},{%4,%5,%6,%7},{%8,%9},{%0,%1,%2,%3};"
        : "+f"(c[0]), "+f"(c[1]), "+f"(c[2]), "+f"(c[3])
        : "r"(a0), "r"(a1), "r"(a2), "r"(a3), "r"(b0), "r"(b1));
}

// fp16 128x128 block, K=64 (4 k16 steps), operands at word-stride STRIDE
template <int STRIDE>
__device__ __forceinline__ void compute_tiles16(const uint32_t* __restrict__ As,
                                                const uint32_t* __restrict__ Bs,
                                                int wm, int wn, int lane,
                                                float acc[4][4][4]) {
#pragma unroll
    for (int ks = 0; ks < 4; ++ks) {
        const int col = ks * 8 + (lane & 3);
        uint32_t a[4][4], b[4][2];
#pragma unroll
        for (int mt = 0; mt < 4; ++mt) {
            int r = wm * 64 + mt * 16 + (lane >> 2);
            a[mt][0] = As[r * STRIDE + col];
            a[mt][1] = As[(r + 8) * STRIDE + col];
            a[mt][2] = As[r * STRIDE + col + 4];
            a[mt][3] = As[(r + 8) * STRIDE + col + 4];
        }
#pragma unroll
        for (int nt = 0; nt < 4; ++nt) {
            int n = wn * 32 + nt * 8 + (lane >> 2);
            b[nt][0] = Bs[n * STRIDE + col];
            b[nt][1] = Bs[n * STRIDE + col + 4];
        }
#pragma unroll
        for (int mt = 0; mt < 4; ++mt)
#pragma unroll
            for (int nt = 0; nt < 4; ++nt)
                mma16(acc[mt][nt], a[mt][0], a[mt][1], a[mt][2], a[mt][3],
                      b[nt][0], b[nt][1]);
    }
}

// ---------------------------------------------------------------------------
// 0) fp16 pre-rounding, one launch
// ---------------------------------------------------------------------------
__global__ void round_all_kernel(const float* __restrict__ tfeat,
                                 const float* __restrict__ wq,
                                 const float* __restrict__ wk,
                                 const float* __restrict__ wv,
                                 const float* __restrict__ wp) {
    const int y = blockIdx.y;
    const float* src;
    __half* dst;
    int n4;
    if (y == 0) { src = tfeat; dst = g_tfh; n4 = BATCH * NT * DIM / 4; }
    else {
        src = (y == 1) ? wq : (y == 2) ? wk : (y == 3) ? wv : wp;
        dst = g_wh + (size_t)(y - 1) * DIM * DIM;
        n4 = DIM * DIM / 4;
    }
    for (int i = blockIdx.x * blockDim.x + threadIdx.x; i < n4;
         i += gridDim.x * blockDim.x) {
        float4 v = ((const float4*)src)[i];
        uint2 o;
        o.x = h2_as_u32(__floats2half2_rn(v.x, v.y));
        o.y = h2_as_u32(__floats2half2_rn(v.z, v.w));
        ((uint2*)dst)[i] = o;
    }
}

// stage a 128-row x 64-half tile (stride 36 words) -- 8 cp16s per row
__device__ __forceinline__ void stage_tile_h(uint32_t dst_base, const __half* src,
                                             int row0, int ld, int k0, int tid) {
#pragma unroll
    for (int u = 0; u < 4; ++u) {
        int idx = tid + u * 256;         // 0..1023
        int row = idx >> 3;              // 0..127
        int seg = idx & 7;               // 0..7, 8 halves each
        cp16(dst_base + (uint32_t)(row * 36 + seg * 4) * 4,
             &src[(size_t)(row0 + row) * ld + k0 + seg * 8]);
    }
}

// ---------------------------------------------------------------------------
// 1) QKV projection, fp16 mma, 3-stage cp.async (K=64/stage). grid (6, 64, 3).
// ---------------------------------------------------------------------------
__global__ __launch_bounds__(256, 2) void qkv_gemm_kernel(
    const float* __restrict__ bq, const float* __restrict__ bk,
    const float* __restrict__ bv)
{
    extern __shared__ uint32_t sm[];
    const uint32_t sbase = (uint32_t)__cvta_generic_to_shared(sm);

    const int z = blockIdx.z;
    const __half* A = g_tfh;
    const __half* W = g_wh + (size_t)z * DIM * DIM;
    const float* bias = (z == 0) ? bq : (z == 1) ? bk : bv;

    const int tid = threadIdx.x;
    const int lane = tid & 31;
    const int wid = tid >> 5;
    const int wm = wid >> 2, wn = wid & 3;
    const int m0 = blockIdx.y * 128;
    const int n0 = blockIdx.x * 128;

    auto stage = [&](int buf, int k0) {
        stage_tile_h(sbase + (uint32_t)(buf * 4608) * 4, A, m0, DIM, k0, tid);
        stage_tile_h(sbase + (uint32_t)(13824 + buf * 4608) * 4, W, n0, DIM, k0, tid);
        cp_commit();
    };

    float acc[4][4][4] = {};
    stage(0, 0);
    stage(1, 64);
    for (int kt = 0; kt < 12; ++kt) {
        if (kt + 2 < 12) { stage((kt + 2) % 3, (kt + 2) * 64); cp_wait<2>(); }
        else if (kt + 1 < 12) cp_wait<1>();
        else cp_wait<0>();
        __syncthreads();
        compute_tiles16<36>(sm + (kt % 3) * 4608, sm + 13824 + (kt % 3) * 4608,
                            wm, wn, lane, acc);
        __syncthreads();
    }

    if (z < 2) {
        __half* out = (z == 0) ? g_qh : g_kh;
#pragma unroll
        for (int mt = 0; mt < 4; ++mt) {
            int row = m0 + wm * 64 + mt * 16 + (lane >> 2);
            int b0i = row >> 10, t0 = row & 1023;
#pragma unroll
            for (int nt = 0; nt < 4; ++nt) {
                int col = n0 + wn * 32 + nt * 8 + ((lane & 3) << 1);
                int h = col >> 6, d = col & 63;
                float bx = bias[col], by = bias[col + 1];
                *(uint32_t*)&out[((size_t)(b0i * NH + h) * NT + t0) * HD + d] =
                    h2_as_u32(__floats2half2_rn(acc[mt][nt][0] + bx, acc[mt][nt][1] + by));
                *(uint32_t*)&out[((size_t)(b0i * NH + h) * NT + t0 + 8) * HD + d] =
                    h2_as_u32(__floats2half2_rn(acc[mt][nt][2] + bx, acc[mt][nt][3] + by));
            }
        }
    } else {
        // transpose through smem: T[t_local][d_local], stride 133 (fp32)
        __syncthreads();
        float* T = (float*)sm;
#pragma unroll
        for (int mt = 0; mt < 4; ++mt) {
            int lr = wm * 64 + mt * 16 + (lane >> 2);
#pragma unroll
            for (int nt = 0; nt < 4; ++nt) {
                int lc = wn * 32 + nt * 8 + ((lane & 3) << 1);
                float bx = bias[n0 + lc], by = bias[n0 + lc + 1];
                T[lr * 133 + lc]           = acc[mt][nt][0] + bx;
                T[lr * 133 + lc + 1]       = acc[mt][nt][1] + by;
                T[(lr + 8) * 133 + lc]     = acc[mt][nt][2] + bx;
                T[(lr + 8) * 133 + lc + 1] = acc[mt][nt][3] + by;
            }
        }
        __syncthreads();
        const int b0i = m0 >> 10;
        const int t00 = m0 & 1023;
#pragma unroll
        for (int u = 0; u < 16; ++u) {
            int idx = tid + u * 256;
            int dcol = idx >> 5;
            int tq = (idx & 31) << 2;
            uint2 v;
            v.x = h2_as_u32(__floats2half2_rn(T[(tq + 0) * 133 + dcol], T[(tq + 1) * 133 + dcol]));
            v.y = h2_as_u32(__floats2half2_rn(T[(tq + 2) * 133 + dcol], T[(tq + 3) * 133 + dcol]));
            int h = (n0 + dcol) >> 6, d = (n0 + dcol) & 63;
            *(uint2*)&g_vt[((size_t)(b0i * NH + h) * HD + d) * NT + t00 + tq] = v;
        }
    }
}

// ---------------------------------------------------------------------------
// 2) merged attention v2: PV fused into phase 1; phase 2 = pure normalize stream.
//    grid (8, 96). smem words: Q[0,4608) K[4608,9216) V[9216,13568) Ps[13568,22272)
//    = 89088 B dynamic -> 2 blocks/SM.
// ---------------------------------------------------------------------------
__global__ __launch_bounds__(256, 2) void attn_kernel(float* __restrict__ attn)
{
    extern __shared__ uint32_t sm[];
    __shared__ float redsum[4][128];
    __shared__ float invs[128];
    const uint32_t sbase = (uint32_t)__cvta_generic_to_shared(sm);

    const int QOFS = 0, KOFS = 4608, VOFS = 9216, POFS = 13568;

    const int tid = threadIdx.x;
    const int lane = tid & 31;
    const int wid = tid >> 5;
    const int wmS = wid >> 2, wnS = wid & 3;   // S layout 2x4 (warp 64x32)
    const int wmP = wid >> 1, wnP = wid & 1;   // PV layout 4x2 (warp 32x32)
    const int m0 = blockIdx.x * 128;
    const int bh = blockIdx.y;

    const __half* Q = g_qh + (size_t)bh * NT * HD;
    const __half* K = g_kh + (size_t)bh * NT * HD;
    const __half* VT = g_vt + (size_t)bh * HD * NT;
    __half* Pp = g_p + (size_t)bh * NT * NT;
    float* ap = attn + (size_t)bh * NT * NT;

    auto stageV = [&](int c0) {
        uint32_t vofs = sbase + (uint32_t)VOFS * 4;
#pragma unroll
        for (int u = 0; u < 4; ++u) {
            int idx = tid + u * 256;       // 0..1023
            int d = idx >> 4;              // 0..63
            int seg = idx & 15;            // 16 cp16 per 256B row
            cp16(vofs + (uint32_t)(d * 68 + seg * 4) * 4, &VT[(size_t)d * NT + c0 + seg * 8]);
        }
    };

    stage_tile_h(sbase + (uint32_t)QOFS * 4, Q, m0, HD, 0, tid);
    stage_tile_h(sbase + (uint32_t)KOFS * 4, K, 0, HD, 0, tid);
    stageV(0);
    cp_commit();

    float acc_o[2][4][4] = {};
    float rsum[4][2] = {};
    uint32_t* const Ps = sm + POFS;
    const uint32_t* const Vs = sm + VOFS;

    for (int ct = 0; ct < 8; ++ct) {
        cp_wait<0>();
        __syncthreads();

        // ---- S = Q K^T ----
        float acc_s[4][4][4] = {};
        compute_tiles16<36>(sm + QOFS, sm + KOFS, wmS, wnS, lane, acc_s);
        __syncthreads();                 // K buffer consumed

        if (ct + 1 < 8)                  // issue next K (commit later with V)
            stage_tile_h(sbase + (uint32_t)KOFS * 4, K, (ct + 1) * 128, HD, 0, tid);

        // ---- exp: global P write + smem Ps + rowsum ----
        const int n0 = ct * 128;
#pragma unroll
        for (int mt = 0; mt < 4; ++mt) {
            int lr = wmS * 64 + mt * 16 + (lane >> 2);
            int row = m0 + lr;
#pragma unroll
            for (int nt = 0; nt < 4; ++nt) {
                int lc = wnS * 32 + nt * 8 + ((lane & 3) << 1);
                float e0 = __expf(acc_s[mt][nt][0] * SCALE);
                float e1 = __expf(acc_s[mt][nt][1] * SCALE);
                float e2 = __expf(acc_s[mt][nt][2] * SCALE);
                float e3 = __expf(acc_s[mt][nt][3] * SCALE);
                uint32_t p0 = h2_as_u32(__floats2half2_rn(e0, e1));
                uint32_t p1 = h2_as_u32(__floats2half2_rn(e2, e3));
                *(uint32_t*)&Pp[(size_t)row * NT + n0 + lc] = p0;
                *(uint32_t*)&Pp[(size_t)(row + 8) * NT + n0 + lc] = p1;
                Ps[lr * 68 + (lc >> 1)] = p0;
                Ps[(lr + 8) * 68 + (lc >> 1)] = p1;
                rsum[mt][0] += e0 + e1;
                rsum[mt][1] += e2 + e3;
            }
        }
        __syncthreads();                 // Ps visible

        // ---- O += P_raw V  (8 k16 steps over this 128-col tile) ----
#pragma unroll
        for (int ks = 0; ks < 8; ++ks) {
            const int col = ks * 8 + (lane & 3);
            uint32_t a[2][4], b[4][2];
#pragma unroll
            for (int mt = 0; mt < 2; ++mt) {
                int r = wmP * 32 + mt * 16 + (lane >> 2);
                int base = r * 68 + col;
                a[mt][0] = Ps[base];
                a[mt][1] = Ps[base + 8 * 68];
                a[mt][2] = Ps[base + 4];
                a[mt][3] = Ps[base + 8 * 68 + 4];
            }
#pragma unroll
            for (int nt = 0; nt < 4; ++nt) {
                int n = wnP * 32 + nt * 8 + (lane >> 2);
                b[nt][0] = Vs[n * 68 + col];
                b[nt][1] = Vs[n * 68 + col + 4];
            }
#pragma unroll
            for (int mt = 0; mt < 2; ++mt)
#pragma unroll
                for (int nt = 0; nt < 4; ++nt)
                    mma16(acc_o[mt][nt], a[mt][0], a[mt][1], a[mt][2], a[mt][3],
                          b[nt][0], b[nt][1]);
        }
        __syncthreads();                 // Vs consumed

        if (ct + 1 < 8) {
            stageV((ct + 1) * 128);
            cp_commit();
        }
    }

    // ---- rowsum reduce -> invs ----
#pragma unroll
    for (int off = 1; off < 4; off <<= 1)
#pragma unroll
        for (int mt = 0; mt < 4; ++mt) {
            rsum[mt][0] += __shfl_xor_sync(0xffffffffu, rsum[mt][0], off);
            rsum[mt][1] += __shfl_xor_sync(0xffffffffu, rsum[mt][1], off);
        }
    if ((lane & 3) == 0) {
#pragma unroll
        for (int mt = 0; mt < 4; ++mt) {
            int r = wmS * 64 + mt * 16 + (lane >> 2);
            redsum[wnS][r] = rsum[mt][0];
            redsum[wnS][r + 8] = rsum[mt][1];
        }
    }
    __syncthreads();
    if (tid < 128)
        invs[tid] = 1.0f / (redsum[0][tid] + redsum[1][tid] + redsum[2][tid] + redsum[3][tid]);
    __syncthreads();

    // ---- epilogue: O * rinv -> g_xh ----
    {
        const int b = bh / NH, h = bh % NH;
        float rvf[2][2];
#pragma unroll
        for (int mt = 0; mt < 2; ++mt) {
            rvf[mt][0] = invs[wmP * 32 + mt * 16 + (lane >> 2)];
            rvf[mt][1] = invs[wmP * 32 + mt * 16 + (lane >> 2) + 8];
        }
#pragma unroll
        for (int mt = 0; mt < 2; ++mt) {
            int row = m0 + wmP * 32 + mt * 16 + (lane >> 2);
#pragma unroll
            for (int nt = 0; nt < 4; ++nt) {
                int d = wnP * 32 + nt * 8 + ((lane & 3) << 1);
                *(uint32_t*)&g_xh[((size_t)b * NT + row) * DIM + h * HD + d] =
                    h2_as_u32(__floats2half2_rn(acc_o[mt][nt][0] * rvf[mt][0],
                                                acc_o[mt][nt][1] * rvf[mt][0]));
                *(uint32_t*)&g_xh[((size_t)b * NT + row + 8) * DIM + h * HD + d] =
                    h2_as_u32(__floats2half2_rn(acc_o[mt][nt][2] * rvf[mt][1],
                                                acc_o[mt][nt][3] * rvf[mt][1]));
            }
        }
    }

    // ---- phase 2: pure normalize stream (no syncs, no smem) ----
    {
        const int rbase = tid >> 3;          // 0..31
        const int cbase = (tid & 7) * 8;     // 0..56
#pragma unroll
        for (int u = 0; u < 4; ++u) {
            int row = rbase + u * 32;
            float iv = invs[row];
            const __half* prow = &Pp[(size_t)(m0 + row) * NT];
            float* arow = &ap[(size_t)(m0 + row) * NT];
#pragma unroll
            for (int c = 0; c < 16; ++c) {
                int col = cbase + c * 64;
                uint4 p = *(const uint4*)&prow[col];
                float2 f0 = __half22float2(*(const __half2*)&p.x);
                float2 f1 = __half22float2(*(const __half2*)&p.y);
                float2 f2 = __half22float2(*(const __half2*)&p.z);
                float2 f3 = __half22float2(*(const __half2*)&p.w);
                __stcs((float4*)&arow[col],
                       make_float4(f0.x * iv, f0.y * iv, f1.x * iv, f1.y * iv));
                __stcs((float4*)&arow[col + 4],
                       make_float4(f2.x * iv, f2.y * iv, f3.x * iv, f3.y * iv));
            }
        }
    }
}

// ---------------------------------------------------------------------------
// 3) output projection, fp16 mma, 3-stage cp.async (K=64/stage). grid (6, 64).
// ---------------------------------------------------------------------------
__global__ __launch_bounds__(256, 2) void proj_gemm_kernel(
    const float* __restrict__ bias, float* __restrict__ out)
{
    extern __shared__ uint32_t sm[];
    const uint32_t sbase = (uint32_t)__cvta_generic_to_shared(sm);

    const __half* A = g_xh;
    const __half* W = g_wh + (size_t)3 * DIM * DIM;

    const int tid = threadIdx.x;
    const int lane = tid & 31;
    const int wid = tid >> 5;
    const int wm = wid >> 2, wn = wid & 3;
    const int m0 = blockIdx.y * 128;
    const int n0 = blockIdx.x * 128;

    auto stage = [&](int buf, int k0) {
        stage_tile_h(sbase + (uint32_t)(buf * 4608) * 4, A, m0, DIM, k0, tid);
        stage_tile_h(sbase + (uint32_t)(13824 + buf * 4608) * 4, W, n0, DIM, k0, tid);
        cp_commit();
    };

    float acc[4][4][4] = {};
    stage(0, 0);
    stage(1, 64);
    for (int kt = 0; kt < 12; ++kt) {
        if (kt + 2 < 12) { stage((kt + 2) % 3, (kt + 2) * 64); cp_wait<2>(); }
        else if (kt + 1 < 12) cp_wait<1>();
        else cp_wait<0>();
        __syncthreads();
        compute_tiles16<36>(sm + (kt % 3) * 4608, sm + 13824 + (kt % 3) * 4608,
                            wm, wn, lane, acc);
        __syncthreads();
    }

#pragma unroll
    for (int mt = 0; mt < 4; ++mt) {
        int row = m0 + wm * 64 + mt * 16 + (lane >> 2);
#pragma unroll
        for (int nt = 0; nt < 4; ++nt) {
            int col = n0 + wn * 32 + nt * 8 + ((lane & 3) << 1);
            float bx = bias[col], by = bias[col + 1];
            *(float2*)&out[(size_t)row * DIM + col] =
                make_float2(acc[mt][nt][0] + bx, acc[mt][nt][1] + by);
            *(float2*)&out[(size_t)(row + 8) * DIM + col] =
                make_float2(acc[mt][nt][2] + bx, acc[mt][nt][3] + by);
        }
    }
}

// ---------------------------------------------------------------------------

extern "C" void kernel_launch(void* const* d_in, const int* in_sizes, int n_in,
                              void* d_out, int out_size)
{
    const float* tfeat = (const float*)d_in[0];
    const float* wq = (const float*)d_in[1];
    const float* bq = (const float*)d_in[2];
    const float* wk = (const float*)d_in[3];
    const float* bk = (const float*)d_in[4];
    const float* wv = (const float*)d_in[5];
    const float* bv = (const float*)d_in[6];
    const float* wp = (const float*)d_in[7];
    const float* bp = (const float*)d_in[8];

    float* xout = (float*)d_out;
    float* attn_out = (float*)d_out + (size_t)BATCH * NT * DIM;

    round_all_kernel<<<dim3(1024, 5), 256>>>(tfeat, wq, wk, wv, wp);

    cudaFuncSetAttribute(qkv_gemm_kernel, cudaFuncAttributeMaxDynamicSharedMemorySize, 110592);
    cudaFuncSetAttribute(attn_kernel, cudaFuncAttributeMaxDynamicSharedMemorySize, 89088);
    cudaFuncSetAttribute(proj_gemm_kernel, cudaFuncAttributeMaxDynamicSharedMemorySize, 110592);

    qkv_gemm_kernel<<<dim3(DIM / 128, (BATCH * NT) / 128, 3), 256, 110592>>>(bq, bk, bv);
    attn_kernel<<<dim3(NT / 128, NBH), 256, 89088>>>(attn_out);
    proj_gemm_kernel<<<dim3(DIM / 128, (BATCH * NT) / 128), 256, 110592>>>(bp, xout);
}

// round 17
// speedup vs baseline: 1.1982x; 1.1982x over previous
#include <cuda_runtime.h>
#include <cuda_fp16.h>
#include <cstdint>

#define BATCH 8
#define NT 1024
#define DIM 768
#define NH 12
#define HD 64
#define SCALE 0.125f
#define NBH (BATCH * NH)

// scratch (allocation-free rule: __device__ globals)
__device__ __half g_qh[NBH * NT * HD];                // Q fp16 [bh][t][d]
__device__ __half g_kh[NBH * NT * HD];                // K fp16 [bh][t][d]
__device__ __half g_vt[NBH * HD * NT];                // V fp16 transposed [bh][d][t]
__device__ __half g_xh[BATCH * NT * DIM];             // attention output, fp16
__device__ __half g_tfh[BATCH * NT * DIM];            // fp16 tfeat
__device__ __half g_wh[4 * DIM * DIM];                // fp16 wq,wk,wv,wp
__device__ __half g_p[(size_t)NBH * NT * NT];         // unnormalized exp scores, fp16

// ---------------------------------------------------------------------------
// helpers
// ---------------------------------------------------------------------------
__device__ __forceinline__ uint32_t h2_as_u32(__half2 h) {
    union { __half2 h2; uint32_t u; } cvt;
    cvt.h2 = h;
    return cvt.u;
}

__device__ __forceinline__ void cp16(uint32_t s, const void* g) {
    asm volatile("cp.async.cg.shared.global [%0], [%1], 16;" :: "r"(s), "l"(g));
}
__device__ __forceinline__ void cp_commit() { asm volatile("cp.async.commit_group;"); }
template <int N> __device__ __forceinline__ void cp_wait() {
    asm volatile("cp.async.wait_group %0;" :: "n"(N));
}

__device__ __forceinline__ void mma16(float* c,
                                      uint32_t a0, uint32_t a1, uint32_t a2, uint32_t a3,
                                      uint32_t b0, uint32_t b1) {
    asm volatile(
        "mma.sync.aligned.m16n8k16.row.col.f32.f16.f16.f32 "
        "{%0,%1,%2,%3},{%4,%5,%6,%7},{%8,%9},{%0,%1,%2,%3};"
        : "+f"(c[0]), "+f"(c[1]), "+f"(c[2]), "+f"(c[3])
        : "r"(a0), "r"(a1), "r"(a2), "r"(a3), "r"(b0), "r"(b1));
}

// fp16 128x128 block, K=64 (4 k16 steps), operands at word-stride STRIDE
template <int STRIDE>
__device__ __forceinline__ void compute_tiles16(const uint32_t* __restrict__ As,
                                                const uint32_t* __restrict__ Bs,
                                                int wm, int wn, int lane,
                                                float acc[4][4][4]) {
#pragma unroll
    for (int ks = 0; ks < 4; ++ks) {
        const int col = ks * 8 + (lane & 3);
        uint32_t a[4][4], b[4][2];
#pragma unroll
        for (int mt = 0; mt < 4; ++mt) {
            int r = wm * 64 + mt * 16 + (lane >> 2);
            a[mt][0] = As[r * STRIDE + col];
            a[mt][1] = As[(r + 8) * STRIDE + col];
            a[mt][2] = As[r * STRIDE + col + 4];
            a[mt][3] = As[(r + 8) * STRIDE + col + 4];
        }
#pragma unroll
        for (int nt = 0; nt < 4; ++nt) {
            int n = wn * 32 + nt * 8 + (lane >> 2);
            b[nt][0] = Bs[n * STRIDE + col];
            b[nt][1] = Bs[n * STRIDE + col + 4];
        }
#pragma unroll
        for (int mt = 0; mt < 4; ++mt)
#pragma unroll
            for (int nt = 0; nt < 4; ++nt)
                mma16(acc[mt][nt], a[mt][0], a[mt][1], a[mt][2], a[mt][3],
                      b[nt][0], b[nt][1]);
    }
}

// ---------------------------------------------------------------------------
// 0) fp16 pre-rounding, one launch
// ---------------------------------------------------------------------------
__global__ void round_all_kernel(const float* __restrict__ tfeat,
                                 const float* __restrict__ wq,
                                 const float* __restrict__ wk,
                                 const float* __restrict__ wv,
                                 const float* __restrict__ wp) {
    const int y = blockIdx.y;
    const float* src;
    __half* dst;
    int n4;
    if (y == 0) { src = tfeat; dst = g_tfh; n4 = BATCH * NT * DIM / 4; }
    else {
        src = (y == 1) ? wq : (y == 2) ? wk : (y == 3) ? wv : wp;
        dst = g_wh + (size_t)(y - 1) * DIM * DIM;
        n4 = DIM * DIM / 4;
    }
    for (int i = blockIdx.x * blockDim.x + threadIdx.x; i < n4;
         i += gridDim.x * blockDim.x) {
        float4 v = ((const float4*)src)[i];
        uint2 o;
        o.x = h2_as_u32(__floats2half2_rn(v.x, v.y));
        o.y = h2_as_u32(__floats2half2_rn(v.z, v.w));
        ((uint2*)dst)[i] = o;
    }
}

// stage a 128-row x 64-half tile (stride 36 words) -- 8 cp16s per row
__device__ __forceinline__ void stage_tile_h(uint32_t dst_base, const __half* src,
                                             int row0, int ld, int k0, int tid) {
#pragma unroll
    for (int u = 0; u < 4; ++u) {
        int idx = tid + u * 256;         // 0..1023
        int row = idx >> 3;              // 0..127
        int seg = idx & 7;               // 0..7, 8 halves each
        cp16(dst_base + (uint32_t)(row * 36 + seg * 4) * 4,
             &src[(size_t)(row0 + row) * ld + k0 + seg * 8]);
    }
}

// ---------------------------------------------------------------------------
// 1) QKV projection, fp16 mma, 3-stage cp.async, ONE sync/iter. grid (6, 64, 3).
// ---------------------------------------------------------------------------
__global__ __launch_bounds__(256, 2) void qkv_gemm_kernel(
    const float* __restrict__ bq, const float* __restrict__ bk,
    const float* __restrict__ bv)
{
    extern __shared__ uint32_t sm[];
    const uint32_t sbase = (uint32_t)__cvta_generic_to_shared(sm);

    const int z = blockIdx.z;
    const __half* A = g_tfh;
    const __half* W = g_wh + (size_t)z * DIM * DIM;
    const float* bias = (z == 0) ? bq : (z == 1) ? bk : bv;

    const int tid = threadIdx.x;
    const int lane = tid & 31;
    const int wid = tid >> 5;
    const int wm = wid >> 2, wn = wid & 3;
    const int m0 = blockIdx.y * 128;
    const int n0 = blockIdx.x * 128;

    auto stage = [&](int buf, int k0) {
        stage_tile_h(sbase + (uint32_t)(buf * 4608) * 4, A, m0, DIM, k0, tid);
        stage_tile_h(sbase + (uint32_t)(13824 + buf * 4608) * 4, W, n0, DIM, k0, tid);
        cp_commit();
    };

    float acc[4][4][4] = {};
    stage(0, 0);
    stage(1, 64);
    for (int kt = 0; kt < 12; ++kt) {
        if (kt + 2 < 12) cp_wait<1>();
        else if (kt + 1 < 12) cp_wait<1>();
        else cp_wait<0>();
        __syncthreads();
        compute_tiles16<36>(sm + (kt % 3) * 4608, sm + 13824 + (kt % 3) * 4608,
                            wm, wn, lane, acc);
        if (kt + 2 < 12) stage((kt + 2) % 3, (kt + 2) * 64);
    }

    if (z < 2) {
        __half* out = (z == 0) ? g_qh : g_kh;
#pragma unroll
        for (int mt = 0; mt < 4; ++mt) {
            int row = m0 + wm * 64 + mt * 16 + (lane >> 2);
            int b0i = row >> 10, t0 = row & 1023;
#pragma unroll
            for (int nt = 0; nt < 4; ++nt) {
                int col = n0 + wn * 32 + nt * 8 + ((lane & 3) << 1);
                int h = col >> 6, d = col & 63;
                float bx = bias[col], by = bias[col + 1];
                *(uint32_t*)&out[((size_t)(b0i * NH + h) * NT + t0) * HD + d] =
                    h2_as_u32(__floats2half2_rn(acc[mt][nt][0] + bx, acc[mt][nt][1] + by));
                *(uint32_t*)&out[((size_t)(b0i * NH + h) * NT + t0 + 8) * HD + d] =
                    h2_as_u32(__floats2half2_rn(acc[mt][nt][2] + bx, acc[mt][nt][3] + by));
            }
        }
    } else {
        // transpose through smem: T[t_local][d_local], stride 133 (fp32)
        __syncthreads();
        float* T = (float*)sm;
#pragma unroll
        for (int mt = 0; mt < 4; ++mt) {
            int lr = wm * 64 + mt * 16 + (lane >> 2);
#pragma unroll
            for (int nt = 0; nt < 4; ++nt) {
                int lc = wn * 32 + nt * 8 + ((lane & 3) << 1);
                float bx = bias[n0 + lc], by = bias[n0 + lc + 1];
                T[lr * 133 + lc]           = acc[mt][nt][0] + bx;
                T[lr * 133 + lc + 1]       = acc[mt][nt][1] + by;
                T[(lr + 8) * 133 + lc]     = acc[mt][nt][2] + bx;
                T[(lr + 8) * 133 + lc + 1] = acc[mt][nt][3] + by;
            }
        }
        __syncthreads();
        const int b0i = m0 >> 10;
        const int t00 = m0 & 1023;
#pragma unroll
        for (int u = 0; u < 16; ++u) {
            int idx = tid + u * 256;
            int dcol = idx >> 5;
            int tq = (idx & 31) << 2;
            uint2 v;
            v.x = h2_as_u32(__floats2half2_rn(T[(tq + 0) * 133 + dcol], T[(tq + 1) * 133 + dcol]));
            v.y = h2_as_u32(__floats2half2_rn(T[(tq + 2) * 133 + dcol], T[(tq + 3) * 133 + dcol]));
            int h = (n0 + dcol) >> 6, d = (n0 + dcol) & 63;
            *(uint2*)&g_vt[((size_t)(b0i * NH + h) * HD + d) * NT + t00 + tq] = v;
        }
    }
}

// ---------------------------------------------------------------------------
// 2) merged attention: one block owns a 128-row stripe of one bh.
//    Phase 1: S = exp(QK^T*SCALE) -> g_p (plain stores, stays in L2),
//             row sums in registers -> invs.
//    Phase 2: re-read own P stripe (L2 hits), write fp32 attn once, PV mma.
//    grid (8, 96). 55296 B dynamic smem.
// ---------------------------------------------------------------------------
__global__ __launch_bounds__(256) void attn_kernel(float* __restrict__ attn)
{
    extern __shared__ uint32_t sm[];
    __shared__ float redsum[4][128];
    __shared__ float invs[128];
    const uint32_t sbase = (uint32_t)__cvta_generic_to_shared(sm);

    const int tid = threadIdx.x;
    const int lane = tid & 31;
    const int wid = tid >> 5;
    const int m0 = blockIdx.x * 128;
    const int bh = blockIdx.y;

    const __half* Q = g_qh + (size_t)bh * NT * HD;
    const __half* K = g_kh + (size_t)bh * NT * HD;
    const __half* VT = g_vt + (size_t)bh * HD * NT;
    __half* Pp = g_p + (size_t)bh * NT * NT;
    float* ap = attn + (size_t)bh * NT * NT;

    // ======================= phase 1: scores + rowsums ======================
    {
        const int wm = wid >> 2, wn = wid & 3;   // 2x4 layout, warp tile 64x32
        const uint32_t qofs = sbase + (uint32_t)9216 * 4;

        stage_tile_h(qofs, Q, m0, HD, 0, tid);
        stage_tile_h(sbase, K, 0, HD, 0, tid);
        cp_commit();

        float rsum[4][2] = {};
        for (int ct = 0; ct < 8; ++ct) {
            if (ct + 1 < 8) {
                stage_tile_h(sbase + (uint32_t)(((ct + 1) & 1) * 4608) * 4,
                             K, (ct + 1) * 128, HD, 0, tid);
                cp_commit();
                cp_wait<1>();
            } else cp_wait<0>();
            __syncthreads();

            float acc[4][4][4] = {};
            compute_tiles16<36>(sm + 9216, sm + (ct & 1) * 4608, wm, wn, lane, acc);

            const int n0 = ct * 128;
#pragma unroll
            for (int mt = 0; mt < 4; ++mt) {
                int row = m0 + wm * 64 + mt * 16 + (lane >> 2);
#pragma unroll
                for (int nt = 0; nt < 4; ++nt) {
                    int col = n0 + wn * 32 + nt * 8 + ((lane & 3) << 1);
                    float e0 = __expf(acc[mt][nt][0] * SCALE);
                    float e1 = __expf(acc[mt][nt][1] * SCALE);
                    float e2 = __expf(acc[mt][nt][2] * SCALE);
                    float e3 = __expf(acc[mt][nt][3] * SCALE);
                    *(__half2*)&Pp[(size_t)row * NT + col] = __floats2half2_rn(e0, e1);
                    *(__half2*)&Pp[(size_t)(row + 8) * NT + col] = __floats2half2_rn(e2, e3);
                    rsum[mt][0] += e0 + e1;
                    rsum[mt][1] += e2 + e3;
                }
            }
            __syncthreads();
        }

#pragma unroll
        for (int off = 1; off < 4; off <<= 1)
#pragma unroll
            for (int mt = 0; mt < 4; ++mt) {
                rsum[mt][0] += __shfl_xor_sync(0xffffffffu, rsum[mt][0], off);
                rsum[mt][1] += __shfl_xor_sync(0xffffffffu, rsum[mt][1], off);
            }
        if ((lane & 3) == 0) {
#pragma unroll
            for (int mt = 0; mt < 4; ++mt) {
                int r = wm * 64 + mt * 16 + (lane >> 2);
                redsum[wn][r] = rsum[mt][0];
                redsum[wn][r + 8] = rsum[mt][1];
            }
        }
        __syncthreads();
        if (tid < 128)
            invs[tid] = 1.0f / (redsum[0][tid] + redsum[1][tid] + redsum[2][tid] + redsum[3][tid]);
        __syncthreads();
    }

    // ======================= phase 2: attn write + PV =======================
    const int wm = wid >> 1, wn = wid & 1;       // 4x2 layout, warp tile 32x32

    const int srow = tid >> 3;                   // 0..31 (+u*32)
    const int sc4 = (tid & 7) * 4;
    float myinv[4];
#pragma unroll
    for (int u = 0; u < 4; ++u) myinv[u] = invs[srow + u * 32];

    float rvf[2][2];
#pragma unroll
    for (int mt = 0; mt < 2; ++mt) {
        rvf[mt][0] = invs[wm * 32 + mt * 16 + (lane >> 2)];
        rvf[mt][1] = invs[wm * 32 + mt * 16 + (lane >> 2) + 8];
    }

    auto stageP = [&](int buf, int k0) {
        uint32_t pofs = sbase + (uint32_t)(buf * 2560) * 4;
#pragma unroll
        for (int u = 0; u < 2; ++u) {
            int idx = tid + u * 256;
            int row = idx >> 2, seg = idx & 3;
            cp16(pofs + (uint32_t)(row * 20 + seg * 4) * 4,
                 &Pp[(size_t)(m0 + row) * NT + k0 + seg * 8]);
        }
    };
    auto stageV = [&](int buf, int k0) {
        uint32_t vofs = sbase + (uint32_t)(5120 + buf * 1280) * 4;
        int d = tid >> 2, seg = tid & 3;
        cp16(vofs + (uint32_t)(d * 20 + seg * 4) * 4,
             &VT[(size_t)d * NT + k0 + seg * 8]);
    };

    stageP(0, 0);
    stageV(0, 0);
    cp_commit();

    float acc[2][4][4] = {};
    for (int kt = 0; kt < 32; ++kt) {
        const int cur = kt & 1;
        if (kt + 1 < 32) {
            stageP((kt + 1) & 1, (kt + 1) * 32);
            stageV((kt + 1) & 1, (kt + 1) * 32);
            cp_commit();
            cp_wait<1>();
        } else cp_wait<0>();
        __syncthreads();

        const uint32_t* Ps = sm + cur * 2560;
        const uint32_t* Vs = sm + 5120 + cur * 1280;

        // write final normalized fp32 attn from fp16 smem
#pragma unroll
        for (int u = 0; u < 4; ++u) {
            int row = srow + u * 32;
            uint2 p2 = *(const uint2*)&Ps[row * 20 + (tid & 7) * 2];
            float2 f0 = __half22float2(*(const __half2*)&p2.x);
            float2 f1 = __half22float2(*(const __half2*)&p2.y);
            float iv = myinv[u];
            float4 v = make_float4(f0.x * iv, f0.y * iv, f1.x * iv, f1.y * iv);
            __stcs((float4*)&ap[(size_t)(m0 + row) * NT + kt * 32 + sc4], v);
        }

        // fp16 mma: O += P_raw V  (2 k16 steps per 32-tile)
#pragma unroll
        for (int ks = 0; ks < 2; ++ks) {
            uint32_t a[2][4], b[4][2];
#pragma unroll
            for (int mt = 0; mt < 2; ++mt) {
                int r = wm * 32 + mt * 16 + (lane >> 2);
                int base = r * 20 + ks * 8 + (lane & 3);
                a[mt][0] = Ps[base];
                a[mt][1] = Ps[base + 160];
                a[mt][2] = Ps[base + 4];
                a[mt][3] = Ps[base + 164];
            }
#pragma unroll
            for (int nt = 0; nt < 4; ++nt) {
                int n = wn * 32 + nt * 8 + (lane >> 2);
                int base = n * 20 + ks * 8 + (lane & 3);
                b[nt][0] = Vs[base];
                b[nt][1] = Vs[base + 4];
            }
#pragma unroll
            for (int mt = 0; mt < 2; ++mt)
#pragma unroll
                for (int nt = 0; nt < 4; ++nt)
                    mma16(acc[mt][nt], a[mt][0], a[mt][1], a[mt][2], a[mt][3],
                          b[nt][0], b[nt][1]);
        }
        __syncthreads();
    }

    const int b = bh / NH, h = bh % NH;
#pragma unroll
    for (int mt = 0; mt < 2; ++mt) {
        int row = m0 + wm * 32 + mt * 16 + (lane >> 2);
#pragma unroll
        for (int nt = 0; nt < 4; ++nt) {
            int d = wn * 32 + nt * 8 + ((lane & 3) << 1);
            *(uint32_t*)&g_xh[((size_t)b * NT + row) * DIM + h * HD + d] =
                h2_as_u32(__floats2half2_rn(acc[mt][nt][0] * rvf[mt][0],
                                            acc[mt][nt][1] * rvf[mt][0]));
            *(uint32_t*)&g_xh[((size_t)b * NT + row + 8) * DIM + h * HD + d] =
                h2_as_u32(__floats2half2_rn(acc[mt][nt][2] * rvf[mt][1],
                                            acc[mt][nt][3] * rvf[mt][1]));
        }
    }
}

// ---------------------------------------------------------------------------
// 3) output projection, fp16 mma, 3-stage cp.async, ONE sync/iter. grid (6, 64).
// ---------------------------------------------------------------------------
__global__ __launch_bounds__(256, 2) void proj_gemm_kernel(
    const float* __restrict__ bias, float* __restrict__ out)
{
    extern __shared__ uint32_t sm[];
    const uint32_t sbase = (uint32_t)__cvta_generic_to_shared(sm);

    const __half* A = g_xh;
    const __half* W = g_wh + (size_t)3 * DIM * DIM;

    const int tid = threadIdx.x;
    const int lane = tid & 31;
    const int wid = tid >> 5;
    const int wm = wid >> 2, wn = wid & 3;
    const int m0 = blockIdx.y * 128;
    const int n0 = blockIdx.x * 128;

    auto stage = [&](int buf, int k0) {
        stage_tile_h(sbase + (uint32_t)(buf * 4608) * 4, A, m0, DIM, k0, tid);
        stage_tile_h(sbase + (uint32_t)(13824 + buf * 4608) * 4, W, n0, DIM, k0, tid);
        cp_commit();
    };

    float acc[4][4][4] = {};
    stage(0, 0);
    stage(1, 64);
    for (int kt = 0; kt < 12; ++kt) {
        if (kt + 1 < 12) cp_wait<1>();
        else cp_wait<0>();
        __syncthreads();
        compute_tiles16<36>(sm + (kt % 3) * 4608, sm + 13824 + (kt % 3) * 4608,
                            wm, wn, lane, acc);
        if (kt + 2 < 12) stage((kt + 2) % 3, (kt + 2) * 64);
    }

#pragma unroll
    for (int mt = 0; mt < 4; ++mt) {
        int row = m0 + wm * 64 + mt * 16 + (lane >> 2);
#pragma unroll
        for (int nt = 0; nt < 4; ++nt) {
            int col = n0 + wn * 32 + nt * 8 + ((lane & 3) << 1);
            float bx = bias[col], by = bias[col + 1];
            *(float2*)&out[(size_t)row * DIM + col] =
                make_float2(acc[mt][nt][0] + bx, acc[mt][nt][1] + by);
            *(float2*)&out[(size_t)(row + 8) * DIM + col] =
                make_float2(acc[mt][nt][2] + bx, acc[mt][nt][3] + by);
        }
    }
}

// ---------------------------------------------------------------------------

extern "C" void kernel_launch(void* const* d_in, const int* in_sizes, int n_in,
                              void* d_out, int out_size)
{
    const float* tfeat = (const float*)d_in[0];
    const float* wq = (const float*)d_in[1];
    const float* bq = (const float*)d_in[2];
    const float* wk = (const float*)d_in[3];
    const float* bk = (const float*)d_in[4];
    const float* wv = (const float*)d_in[5];
    const float* bv = (const float*)d_in[6];
    const float* wp = (const float*)d_in[7];
    const float* bp = (const float*)d_in[8];

    float* xout = (float*)d_out;
    float* attn_out = (float*)d_out + (size_t)BATCH * NT * DIM;

    round_all_kernel<<<dim3(1024, 5), 256>>>(tfeat, wq, wk, wv, wp);

    cudaFuncSetAttribute(qkv_gemm_kernel, cudaFuncAttributeMaxDynamicSharedMemorySize, 110592);
    cudaFuncSetAttribute(attn_kernel, cudaFuncAttributeMaxDynamicSharedMemorySize, 55296);
    cudaFuncSetAttribute(proj_gemm_kernel, cudaFuncAttributeMaxDynamicSharedMemorySize, 110592);

    qkv_gemm_kernel<<<dim3(DIM / 128, (BATCH * NT) / 128, 3), 256, 110592>>>(bq, bk, bv);
    attn_kernel<<<dim3(NT / 128, NBH), 256, 55296>>>(attn_out);
    proj_gemm_kernel<<<dim3(DIM / 128, (BATCH * NT) / 128), 256, 110592>>>(bp, xout);
}